// round 2
// baseline (speedup 1.0000x reference)
#include <cuda_runtime.h>
#include <cuda_bf16.h>
#include <stdint.h>

// Problem constants
#define B_TOK 8192
#define DIM   2048
#define NEXP  8

// GEMM tiling
#define BM 128
#define BN 128
#define BK 32
#define TM 8
#define TN 8
#define NTHREADS 256

// -------- device scratch (no allocations allowed) --------
__device__ int d_counts[NEXP];
__device__ int d_fill[NEXP];
__device__ int d_offsets[NEXP + 1];
__device__ int d_perm[B_TOK];
__device__ int d_is64;   // 1 if module_indices buffer is int64, 0 if int32

// -------- dtype detection --------
// View idx buffer as int32[B_TOK] (safe under either dtype: int64 buffer is
// 2x larger). If underlying data is little-endian int64 with small values,
// all odd int32 positions are zero. If int32, odd positions are random 0..7.
__global__ void k_detect(const int* __restrict__ v32) {
    int i = blockIdx.x * blockDim.x + threadIdx.x;   // 0..B_TOK-1
    if (i < B_TOK && (i & 1) && v32[i] != 0) {
        d_is64 = 0;
    }
}

__global__ void k_zero() {
    int t = threadIdx.x;
    if (t < NEXP) { d_counts[t] = 0; d_fill[t] = 0; }
    if (t == 0) d_is64 = 1;   // default: int64; detection clears if evidence
}

__device__ __forceinline__ int expert_of(const int* v32, int i) {
    int e = d_is64 ? v32[2 * i] : v32[i];
    return e;
}

// -------- sort kernels --------
__global__ void k_hist(const int* __restrict__ v32) {
    int i = blockIdx.x * blockDim.x + threadIdx.x;
    if (i < B_TOK) {
        int e = expert_of(v32, i);
        if (e >= 0 && e < NEXP) atomicAdd(&d_counts[e], 1);
    }
}

__global__ void k_scan() {
    int acc = 0;
    d_offsets[0] = 0;
    for (int e = 0; e < NEXP; e++) {
        acc += d_counts[e];
        d_offsets[e + 1] = acc;
    }
}

__global__ void k_scatter(const int* __restrict__ v32) {
    int i = blockIdx.x * blockDim.x + threadIdx.x;
    if (i < B_TOK) {
        int e = expert_of(v32, i);
        if (e >= 0 && e < NEXP) {
            int pos = d_offsets[e] + atomicAdd(&d_fill[e], 1);
            d_perm[pos] = i;
        }
    }
}

// -------- grouped GEMM --------
// out[perm_row] = x[perm_row] @ W[e] + b[e]
// W[e] is [D][D] row-major: out[i][j] = sum_d x[i][d] * W[e][d*D + j]
__global__ void __launch_bounds__(NTHREADS)
k_gemm(const float* __restrict__ x,
       const float* __restrict__ W,
       const float* __restrict__ bias,
       float* __restrict__ out)
{
    const int e  = blockIdx.z;
    const int start = d_offsets[e];
    const int cnt   = d_offsets[e + 1] - start;
    const int m0 = blockIdx.y * BM;
    if (m0 >= cnt) return;               // empty tile for this expert
    const int n0 = blockIdx.x * BN;

    __shared__ float As[BK][BM];          // A transposed: As[k][m]
    __shared__ float Bs[BK][BN];
    __shared__ int   rows[BM];

    const int tid = threadIdx.x;

    // gather row indices for this m-tile
    if (tid < BM) {
        int m = m0 + tid;
        rows[tid] = (m < cnt) ? d_perm[start + m] : -1;
    }
    __syncthreads();

    const float* Wm = W + (size_t)e * DIM * DIM;

    float acc[TM][TN];
#pragma unroll
    for (int i = 0; i < TM; i++)
#pragma unroll
        for (int j = 0; j < TN; j++)
            acc[i][j] = 0.0f;

    const int tx = tid & 15;   // 0..15 -> n
    const int ty = tid >> 4;   // 0..15 -> m

    for (int k0 = 0; k0 < DIM; k0 += BK) {
        // ---- load A tile (gathered rows), 128x32 floats = 1024 float4 ----
#pragma unroll
        for (int i = 0; i < 4; i++) {
            int f  = tid + i * NTHREADS;
            int r  = f >> 3;
            int c4 = (f & 7) << 2;
            int grow = rows[r];
            float4 v;
            if (grow >= 0) {
                v = *(const float4*)(x + (size_t)grow * DIM + k0 + c4);
            } else {
                v = make_float4(0.f, 0.f, 0.f, 0.f);
            }
            As[c4 + 0][r] = v.x;
            As[c4 + 1][r] = v.y;
            As[c4 + 2][r] = v.z;
            As[c4 + 3][r] = v.w;
        }
        // ---- load B tile, 32x128 floats = 1024 float4, fully coalesced ----
#pragma unroll
        for (int i = 0; i < 4; i++) {
            int f  = tid + i * NTHREADS;
            int r  = f >> 5;
            int c4 = (f & 31) << 2;
            float4 v = *(const float4*)(Wm + (size_t)(k0 + r) * DIM + n0 + c4);
            *(float4*)&Bs[r][c4] = v;
        }
        __syncthreads();

        // ---- compute ----
#pragma unroll
        for (int kk = 0; kk < BK; kk++) {
            float a[TM], bb[TN];
            float4 a0 = *(const float4*)&As[kk][ty * TM];
            float4 a1 = *(const float4*)&As[kk][ty * TM + 4];
            a[0] = a0.x; a[1] = a0.y; a[2] = a0.z; a[3] = a0.w;
            a[4] = a1.x; a[5] = a1.y; a[6] = a1.z; a[7] = a1.w;
            float4 b0 = *(const float4*)&Bs[kk][tx * TN];
            float4 b1 = *(const float4*)&Bs[kk][tx * TN + 4];
            bb[0] = b0.x; bb[1] = b0.y; bb[2] = b0.z; bb[3] = b0.w;
            bb[4] = b1.x; bb[5] = b1.y; bb[6] = b1.z; bb[7] = b1.w;
#pragma unroll
            for (int i = 0; i < TM; i++)
#pragma unroll
                for (int j = 0; j < TN; j++)
                    acc[i][j] = fmaf(a[i], bb[j], acc[i][j]);
        }
        __syncthreads();
    }

    // ---- epilogue: add bias, scatter rows ----
    const float* be = bias + (size_t)e * DIM;
#pragma unroll
    for (int i = 0; i < TM; i++) {
        int m = ty * TM + i;
        int grow = rows[m];
        if (grow < 0) continue;
        float* orow = out + (size_t)grow * DIM + n0 + tx * TN;
#pragma unroll
        for (int j = 0; j < TN; j += 4) {
            float4 bv = *(const float4*)(be + n0 + tx * TN + j);
            float4 o;
            o.x = acc[i][j + 0] + bv.x;
            o.y = acc[i][j + 1] + bv.y;
            o.z = acc[i][j + 2] + bv.z;
            o.w = acc[i][j + 3] + bv.w;
            *(float4*)(orow + j) = o;
        }
    }
}

extern "C" void kernel_launch(void* const* d_in, const int* in_sizes, int n_in,
                              void* d_out, int out_size)
{
    // Identify inputs by element count (robust to metadata ordering):
    //   x: B*D = 16777216, W: E*D*D = 33554432, b: E*D = 16384, idx: B = 8192
    const float* x = nullptr;
    const float* W = nullptr;
    const float* b = nullptr;
    const void*  idx = nullptr;
    for (int i = 0; i < n_in; i++) {
        long long sz = in_sizes[i];
        if      (sz == (long long)B_TOK * DIM)       x   = (const float*)d_in[i];
        else if (sz == (long long)NEXP * DIM * DIM)  W   = (const float*)d_in[i];
        else if (sz == (long long)NEXP * DIM)        b   = (const float*)d_in[i];
        else if (sz == (long long)B_TOK)             idx = d_in[i];
    }
    float* out = (float*)d_out;                      // [B, D]
    const int* v32 = (const int*)idx;

    k_zero<<<1, 32>>>();
    k_detect<<<B_TOK / 256, 256>>>(v32);
    k_hist<<<B_TOK / 256, 256>>>(v32);
    k_scan<<<1, 1>>>();
    k_scatter<<<B_TOK / 256, 256>>>(v32);

    dim3 grid(DIM / BN, B_TOK / BM, NEXP);   // (16, 64, 8); most m-tiles exit early
    k_gemm<<<grid, NTHREADS>>>(x, W, b, out);
}

// round 4
// speedup vs baseline: 5.2989x; 5.2989x over previous
#include <cuda_runtime.h>
#include <cuda_fp16.h>
#include <stdint.h>

#define B_TOK 8192
#define DIM   2048
#define NEXP  8

#define BM 128
#define BN 128
#define BK 64            // fp16 elems per k-chunk => 128B rows (SW128)
#define NCHUNKS (DIM / BK)
#define STAGES 3
#define GTHREADS 256

// Stage layout: A (128x64 fp16 =16KB) then B (128x64 fp16 =16KB)
#define STAGE_SZ 32768
#define OFF_B    16384
#define OFF_ROWS (STAGES * STAGE_SZ)          // 98304
#define SMEM_REQ (OFF_ROWS + 512 + 1024)      // + rows[] + align slack

// -------- device scratch --------
__device__ int d_counts[NEXP];
__device__ int d_fill[NEXP];
__device__ int d_offsets[NEXP + 1];
__device__ int d_perm[B_TOK];
__device__ int d_is64;

__device__ __half g_xh[(size_t)B_TOK * DIM];              // sorted by expert, fp16
__device__ __half g_wt[(size_t)NEXP * DIM * DIM];         // W transposed: [e][n][k], fp16

// ======================= helpers =======================
__device__ __forceinline__ uint32_t smem_u32(const void* p) {
    uint32_t a;
    asm("{ .reg .u64 t; cvta.to.shared.u64 t, %1; cvt.u32.u64 %0, t; }" : "=r"(a) : "l"(p));
    return a;
}
__device__ __forceinline__ uint32_t sw128(uint32_t off) { return off ^ ((off >> 3) & 0x70); }

__device__ __forceinline__ void cp16(uint32_t dst, const void* src) {
    asm volatile("cp.async.cg.shared.global [%0], [%1], 16;" :: "r"(dst), "l"(src) : "memory");
}
__device__ __forceinline__ void ldsm_x4(uint32_t* r, uint32_t addr) {
    asm volatile("ldmatrix.sync.aligned.m8n8.x4.shared.b16 {%0,%1,%2,%3}, [%4];"
                 : "=r"(r[0]), "=r"(r[1]), "=r"(r[2]), "=r"(r[3]) : "r"(addr));
}
__device__ __forceinline__ void mma16816(float* d, const uint32_t* a, uint32_t b0, uint32_t b1) {
    asm volatile(
        "mma.sync.aligned.m16n8k16.row.col.f32.f16.f16.f32 "
        "{%0,%1,%2,%3}, {%4,%5,%6,%7}, {%8,%9}, {%0,%1,%2,%3};"
        : "+f"(d[0]), "+f"(d[1]), "+f"(d[2]), "+f"(d[3])
        : "r"(a[0]), "r"(a[1]), "r"(a[2]), "r"(a[3]), "r"(b0), "r"(b1));
}

// ======================= sort / detect =======================
__global__ void k_zero() {
    int t = threadIdx.x;
    if (t < NEXP) { d_counts[t] = 0; d_fill[t] = 0; }
    if (t == 0) d_is64 = 1;
}
__global__ void k_detect(const int* __restrict__ v32) {
    int i = blockIdx.x * blockDim.x + threadIdx.x;
    if (i < B_TOK && (i & 1) && v32[i] != 0) d_is64 = 0;
}
__device__ __forceinline__ int expert_of(const int* v, int i) { return d_is64 ? v[2 * i] : v[i]; }
__global__ void k_hist(const int* __restrict__ v) {
    int i = blockIdx.x * blockDim.x + threadIdx.x;
    if (i < B_TOK) { int e = expert_of(v, i); if (e >= 0 && e < NEXP) atomicAdd(&d_counts[e], 1); }
}
__global__ void k_scan() {
    int acc = 0; d_offsets[0] = 0;
    for (int e = 0; e < NEXP; e++) { acc += d_counts[e]; d_offsets[e + 1] = acc; }
}
__global__ void k_scatter(const int* __restrict__ v) {
    int i = blockIdx.x * blockDim.x + threadIdx.x;
    if (i < B_TOK) {
        int e = expert_of(v, i);
        if (e >= 0 && e < NEXP) { int pos = d_offsets[e] + atomicAdd(&d_fill[e], 1); d_perm[pos] = i; }
    }
}

// ======================= conversions =======================
__global__ void k_convx(const float* __restrict__ x) {
    int p = blockIdx.x;
    int grow = d_perm[p];
    const float4* src = (const float4*)(x + (size_t)grow * DIM);
    __half2* dst = (__half2*)(g_xh + (size_t)p * DIM);
    for (int c = threadIdx.x; c < DIM / 4; c += blockDim.x) {
        float4 v = src[c];
        dst[c * 2 + 0] = __floats2half2_rn(v.x, v.y);
        dst[c * 2 + 1] = __floats2half2_rn(v.z, v.w);
    }
}
__global__ void k_convw(const float* __restrict__ W) {
    __shared__ float t[32][33];
    int e = blockIdx.z, k0 = blockIdx.y * 32, n0 = blockIdx.x * 32;
    int j = threadIdx.x, i0 = threadIdx.y;   // 32 x 8
    const float* Wb = W + (size_t)e * DIM * DIM;
#pragma unroll
    for (int ii = 0; ii < 4; ii++) {
        int k = i0 + ii * 8;
        t[k][j] = Wb[(size_t)(k0 + k) * DIM + n0 + j];
    }
    __syncthreads();
#pragma unroll
    for (int ii = 0; ii < 4; ii++) {
        int nl = i0 + ii * 8;
        float v = t[j][nl];                               // W[k0+j][n0+nl]
        size_t off = ((size_t)e * DIM + (n0 + nl)) * DIM + k0 + j;
        g_wt[off] = __float2half_rn(v);
    }
}

// ======================= grouped GEMM =======================
__device__ __forceinline__ void load_stage(uint32_t stage, int k0, int e, int start, int cnt,
                                           int m0, int n0, int tid) {
#pragma unroll
    for (int i = 0; i < 4; i++) {        // A: 128 rows x 8 chunks of 16B = 1024 granules
        int g = tid + i * GTHREADS;
        int r = g >> 3, c = g & 7;
        int m = m0 + r; if (m >= cnt) m = cnt - 1;
        const __half* src = g_xh + (size_t)(start + m) * DIM + k0 + c * 8;
        cp16(stage + sw128((uint32_t)(r * 128 + c * 16)), src);
    }
#pragma unroll
    for (int i = 0; i < 4; i++) {        // B: 128 n-rows x 8 chunks = 1024 granules
        int g = tid + i * GTHREADS;
        int r = g >> 3, c = g & 7;
        const __half* src = g_wt + ((size_t)e * DIM + n0 + r) * DIM + k0 + c * 8;
        cp16(stage + OFF_B + sw128((uint32_t)(r * 128 + c * 16)), src);
    }
}

__global__ void __launch_bounds__(GTHREADS, 1)
k_gemm(const float* __restrict__ bias, float* __restrict__ out)
{
    const int e = blockIdx.z;
    const int start = d_offsets[e];
    const int cnt = d_offsets[e + 1] - start;
    const int m0 = blockIdx.y * BM;
    if (m0 >= cnt) return;
    const int n0 = blockIdx.x * BN;

    extern __shared__ char smraw[];
    const uint32_t A0 = (smem_u32(smraw) + 1023u) & ~1023u;

    const int tid = threadIdx.x;
    const int wid = tid >> 5;
    const int lane = tid & 31;
    const int warp_m = wid >> 2;     // 0..1 -> 64-row slice
    const int warp_n = wid & 3;      // 0..3 -> 32-col slice

    // gather row indices
    int* rows = (int*)(smraw + ((A0 + OFF_ROWS) - smem_u32(smraw)));
    if (tid < BM) {
        int m = m0 + tid;
        rows[tid] = (m < cnt) ? d_perm[start + m] : -1;
    }

    // prologue: stages 0..STAGES-2
#pragma unroll
    for (int s = 0; s < STAGES - 1; s++) {
        load_stage(A0 + s * STAGE_SZ, s * BK, e, start, cnt, m0, n0, tid);
        asm volatile("cp.async.commit_group;" ::: "memory");
    }

    float acc[4][4][4];
#pragma unroll
    for (int i = 0; i < 4; i++)
#pragma unroll
        for (int j = 0; j < 4; j++)
#pragma unroll
            for (int q = 0; q < 4; q++) acc[i][j][q] = 0.0f;

    for (int c = 0; c < NCHUNKS; c++) {
        if (c + STAGES - 1 < NCHUNKS) {
            load_stage(A0 + ((c + STAGES - 1) % STAGES) * STAGE_SZ,
                       (c + STAGES - 1) * BK, e, start, cnt, m0, n0, tid);
        }
        asm volatile("cp.async.commit_group;" ::: "memory");
        asm volatile("cp.async.wait_group %0;" :: "n"(STAGES - 1) : "memory");
        __syncthreads();

        const uint32_t aA = A0 + (c % STAGES) * STAGE_SZ;
        const uint32_t aB = aA + OFF_B;
        const int lrow = lane & 15;
        const int lcol16 = (lane >> 4) << 4;

#pragma unroll
        for (int ks = 0; ks < 4; ks++) {
            uint32_t af[4][4];
#pragma unroll
            for (int i = 0; i < 4; i++) {
                uint32_t off = (uint32_t)((warp_m * 64 + i * 16 + lrow) * 128 + ks * 32 + lcol16);
                ldsm_x4(af[i], aA + sw128(off));
            }
            uint32_t bf[2][4];
#pragma unroll
            for (int g = 0; g < 2; g++) {
                uint32_t off = (uint32_t)((warp_n * 32 + g * 16 + lrow) * 128 + ks * 32 + lcol16);
                ldsm_x4(bf[g], aB + sw128(off));
            }
#pragma unroll
            for (int i = 0; i < 4; i++)
#pragma unroll
                for (int j = 0; j < 4; j++)
                    mma16816(acc[i][j], af[i], bf[j >> 1][j & 1], bf[j >> 1][(j & 1) + 2]);
        }
        __syncthreads();
    }

    // epilogue: add bias, scatter rows
    const float* be = bias + (size_t)e * DIM;
#pragma unroll
    for (int i = 0; i < 4; i++) {
#pragma unroll
        for (int half = 0; half < 2; half++) {
            int mloc = warp_m * 64 + i * 16 + (lane >> 2) + half * 8;
            int grow = rows[mloc];
            if (grow < 0) continue;
            float* orow = out + (size_t)grow * DIM;
#pragma unroll
            for (int j = 0; j < 4; j++) {
                int col = n0 + warp_n * 32 + j * 8 + (lane & 3) * 2;
                float2 bb = *(const float2*)(be + col);
                float2 o;
                o.x = acc[i][j][half * 2 + 0] + bb.x;
                o.y = acc[i][j][half * 2 + 1] + bb.y;
                *(float2*)(orow + col) = o;
            }
        }
    }
}

// ======================= host =======================
extern "C" void kernel_launch(void* const* d_in, const int* in_sizes, int n_in,
                              void* d_out, int out_size)
{
    const float* x = nullptr;
    const float* W = nullptr;
    const float* b = nullptr;
    const void* idx = nullptr;
    for (int i = 0; i < n_in; i++) {
        long long sz = in_sizes[i];
        if      (sz == (long long)B_TOK * DIM)      x = (const float*)d_in[i];
        else if (sz == (long long)NEXP * DIM * DIM) W = (const float*)d_in[i];
        else if (sz == (long long)NEXP * DIM)       b = (const float*)d_in[i];
        else if (sz == (long long)B_TOK)            idx = d_in[i];
    }
    float* out = (float*)d_out;
    const int* v32 = (const int*)idx;

    cudaFuncSetAttribute(k_gemm, cudaFuncAttributeMaxDynamicSharedMemorySize, SMEM_REQ);

    k_zero<<<1, 32>>>();
    k_detect<<<B_TOK / 256, 256>>>(v32);
    k_hist<<<B_TOK / 256, 256>>>(v32);
    k_scan<<<1, 1>>>();
    k_scatter<<<B_TOK / 256, 256>>>(v32);

    k_convx<<<B_TOK, 256>>>(x);
    dim3 wgrid(DIM / 32, DIM / 32, NEXP);
    k_convw<<<wgrid, dim3(32, 8)>>>(W);

    dim3 ggrid(DIM / BN, B_TOK / BM, NEXP);   // (16, 64, 8); extra m-tiles exit early
    k_gemm<<<ggrid, GTHREADS, SMEM_REQ>>>(b, out);
}

// round 5
// speedup vs baseline: 5.6135x; 1.0594x over previous
#include <cuda_runtime.h>
#include <cuda_fp16.h>
#include <stdint.h>

#define B_TOK 8192
#define DIM   2048
#define NEXP  8

#define BM 128
#define BN 256
#define BK 64
#define NKC (DIM / BK)          // 32 k-chunks
#define NNT (DIM / BN)          // 8 n-tiles
#define MAXTILES 72             // 64 + 8 (padding per expert)
#define STAGES 4
#define GTHREADS 256

#define TILE_A 16384            // 128 x 64 fp16
#define TILE_B 32768            // 256 x 64 fp16
#define STAGE_SZ 49152
#define OFF_B 16384
#define OFF_MB (STAGES * STAGE_SZ)       // 196608
#define OFF_ROWS (OFF_MB + 64)
#define SMEM_REQ (OFF_ROWS + 512 + 1024)

// -------- device scratch --------
__device__ int d_counts[NEXP];
__device__ int d_fill[NEXP];
__device__ int d_offsets[NEXP + 1];
__device__ int d_poff[NEXP + 1];         // padded (multiple of 128) offsets
__device__ int d_is64;
__device__ int d_perm[MAXTILES * 128];   // -1 in padded slots

__device__ __align__(128) char g_xa[(size_t)MAXTILES * NKC * TILE_A];          // ~36 MB
__device__ __align__(128) char g_wb[(size_t)NEXP * NNT * NKC * TILE_B];        // 64 MB

// ======================= helpers =======================
__device__ __forceinline__ uint32_t smem_u32(const void* p) {
    uint32_t a;
    asm("{ .reg .u64 t; cvta.to.shared.u64 t, %1; cvt.u32.u64 %0, t; }" : "=r"(a) : "l"(p));
    return a;
}
__device__ __forceinline__ uint32_t sw128(uint32_t off) { return off ^ ((off >> 3) & 0x70); }

__device__ __forceinline__ void ldsm_x4(uint32_t* r, uint32_t addr) {
    asm volatile("ldmatrix.sync.aligned.m8n8.x4.shared.b16 {%0,%1,%2,%3}, [%4];"
                 : "=r"(r[0]), "=r"(r[1]), "=r"(r[2]), "=r"(r[3]) : "r"(addr));
}
__device__ __forceinline__ void mma16816(float* d, const uint32_t* a, uint32_t b0, uint32_t b1) {
    asm volatile(
        "mma.sync.aligned.m16n8k16.row.col.f32.f16.f16.f32 "
        "{%0,%1,%2,%3}, {%4,%5,%6,%7}, {%8,%9}, {%0,%1,%2,%3};"
        : "+f"(d[0]), "+f"(d[1]), "+f"(d[2]), "+f"(d[3])
        : "r"(a[0]), "r"(a[1]), "r"(a[2]), "r"(a[3]), "r"(b0), "r"(b1));
}
__device__ __forceinline__ void bulk_g2s(uint32_t dst, const void* src, uint32_t bytes, uint32_t mbar) {
    asm volatile(
        "{\n\t.reg .u64 g;\n\tcvta.to.global.u64 g, %1;\n\t"
        "cp.async.bulk.shared::cluster.global.mbarrier::complete_tx::bytes [%0], [g], %2, [%3];\n\t}"
        :: "r"(dst), "l"(src), "r"(bytes), "r"(mbar) : "memory");
}
#define MBARRIER_INIT(addr, cnt) \
    asm volatile("mbarrier.init.shared.b64 [%0], %1;" :: "r"((uint32_t)(addr)), "r"((uint32_t)(cnt)) : "memory")
#define MBARRIER_EXPECT_TX(addr, tx) \
    asm volatile("mbarrier.arrive.expect_tx.shared.b64 _, [%0], %1;" :: "r"((uint32_t)(addr)), "r"((uint32_t)(tx)) : "memory")
#define MBARRIER_WAIT_PARITY(addr, par) do { \
    uint32_t _m = (uint32_t)(addr); uint32_t _p = (uint32_t)(par); uint32_t _done; \
    asm volatile("{\n\t.reg .pred p;\n\t" \
        "mbarrier.try_wait.parity.acquire.cta.shared::cta.b64 p, [%1], %2;\n\t" \
        "selp.b32 %0, 1, 0, p;\n\t}" : "=r"(_done) : "r"(_m), "r"(_p) : "memory"); \
    if (!_done) { \
        asm volatile("{\n\t.reg .pred P1;\n\t" \
            "WL_%=:\n\tmbarrier.try_wait.parity.acquire.cta.shared::cta.b64 P1, [%0], %1, 0x989680;\n\t" \
            "@P1 bra.uni WD_%=;\n\tbra.uni WL_%=;\n\tWD_%=:\n\t}" \
            :: "r"(_m), "r"(_p) : "memory"); \
    } \
} while (0)

// ======================= sort / detect =======================
__global__ void k_zero() {
    int i = blockIdx.x * blockDim.x + threadIdx.x;
    if (i < MAXTILES * 128) d_perm[i] = -1;
    if (blockIdx.x == 0 && threadIdx.x < NEXP) { d_counts[threadIdx.x] = 0; d_fill[threadIdx.x] = 0; }
    if (blockIdx.x == 0 && threadIdx.x == 0) d_is64 = 1;
}
__global__ void k_detect(const int* __restrict__ v32) {
    int i = blockIdx.x * blockDim.x + threadIdx.x;
    if (i < B_TOK && (i & 1) && v32[i] != 0) d_is64 = 0;
}
__device__ __forceinline__ int expert_of(const int* v, int i) { return d_is64 ? v[2 * i] : v[i]; }
__global__ void k_hist(const int* __restrict__ v) {
    int i = blockIdx.x * blockDim.x + threadIdx.x;
    if (i < B_TOK) { int e = expert_of(v, i); if (e >= 0 && e < NEXP) atomicAdd(&d_counts[e], 1); }
}
__global__ void k_scan() {
    int acc = 0, pacc = 0;
    d_offsets[0] = 0; d_poff[0] = 0;
    for (int e = 0; e < NEXP; e++) {
        int c = d_counts[e];
        acc += c; pacc += ((c + 127) / 128) * 128;
        d_offsets[e + 1] = acc; d_poff[e + 1] = pacc;
    }
}
__global__ void k_scatter(const int* __restrict__ v) {
    int i = blockIdx.x * blockDim.x + threadIdx.x;
    if (i < B_TOK) {
        int e = expert_of(v, i);
        if (e >= 0 && e < NEXP) { int pos = d_poff[e] + atomicAdd(&d_fill[e], 1); d_perm[pos] = i; }
    }
}

// ======================= conversions (tiled + pre-swizzled) =======================
// A tile (tile, kc): 128 rows x 64 fp16, SW128-swizzled, 16KB contiguous.
__global__ void k_convx(const float* __restrict__ x) {
    __shared__ int pm[128];
    const int t = threadIdx.x, tile = blockIdx.x, kc = blockIdx.y;
    if (t < 128) pm[t] = d_perm[tile * 128 + t];
    __syncthreads();
    char* dst = g_xa + ((size_t)(tile * NKC + kc)) * TILE_A;
#pragma unroll
    for (int i = 0; i < 8; i++) {
        int v = i * 256 + t;          // 0..2047 ; 16 float4 per row
        int r = v >> 4, f = v & 15;
        int p = pm[r];
        uint2 hv = make_uint2(0u, 0u);
        if (p >= 0) {
            float4 w = *(const float4*)(x + (size_t)p * DIM + kc * BK + f * 4);
            __half2 h0 = __floats2half2_rn(w.x, w.y);
            __half2 h1 = __floats2half2_rn(w.z, w.w);
            hv.x = *(uint32_t*)&h0; hv.y = *(uint32_t*)&h1;
        }
        *(uint2*)(dst + sw128((uint32_t)(r * 128 + f * 8))) = hv;
    }
}

// B tile (e, nt, kc): transpose W[k][n] -> [n][k], 256 rows x 64 fp16, SW128, 32KB contiguous.
#define KP 72
__global__ void k_convw(const float* __restrict__ W) {
    __shared__ __half ts[256 * KP];
    const int nt = blockIdx.x, kc = blockIdx.y, e = blockIdx.z;
    const int t = threadIdx.x;
    const float* Wb = W + ((size_t)e * DIM + kc * BK) * DIM + nt * BN;
#pragma unroll
    for (int i = 0; i < 16; i++) {
        int v = i * 256 + t;          // 0..4095 ; 64 float4 per k-row
        int k = v >> 6, c4 = v & 63;
        float4 w = *(const float4*)(Wb + (size_t)k * DIM + c4 * 4);
        int n = c4 * 4;
        ts[(n + 0) * KP + k] = __float2half_rn(w.x);
        ts[(n + 1) * KP + k] = __float2half_rn(w.y);
        ts[(n + 2) * KP + k] = __float2half_rn(w.z);
        ts[(n + 3) * KP + k] = __float2half_rn(w.w);
    }
    __syncthreads();
    char* dst = g_wb + ((size_t)((e * NNT + nt) * NKC + kc)) * TILE_B;
    const int n = t;
#pragma unroll
    for (int q = 0; q < 8; q++) {
        uint4 val = *(const uint4*)&ts[n * KP + q * 8];    // 144B row stride: 16B aligned
        *(uint4*)(dst + sw128((uint32_t)(n * 128 + q * 16))) = val;
    }
}

// ======================= grouped GEMM =======================
__device__ __forceinline__ void issue_stage(uint32_t A0, uint32_t mb, int chunk, int stage,
                                            int mt, int e, int nt) {
    uint32_t bar = mb + stage * 8;
    MBARRIER_EXPECT_TX(bar, (uint32_t)STAGE_SZ);
    const char* asrc = g_xa + ((size_t)(mt * NKC + chunk)) * TILE_A;
    const char* bsrc = g_wb + ((size_t)((e * NNT + nt) * NKC + chunk)) * TILE_B;
    uint32_t sb = A0 + stage * STAGE_SZ;
    bulk_g2s(sb, asrc, TILE_A, bar);
    bulk_g2s(sb + OFF_B, bsrc, TILE_B, bar);
}

__global__ void __launch_bounds__(GTHREADS, 1)
k_gemm(const float* __restrict__ bias, float* __restrict__ out)
{
    const int m0p = blockIdx.y * BM;
    if (m0p >= d_poff[NEXP]) return;
    int e = 0;
#pragma unroll
    for (int i = 0; i < NEXP; i++) if (m0p >= d_poff[i + 1]) e = i + 1;

    const int mt = blockIdx.y;
    const int nt = blockIdx.x;
    const int n0 = nt * BN;

    extern __shared__ char smraw[];
    const uint32_t A0 = (smem_u32(smraw) + 1023u) & ~1023u;
    const uint32_t mb = A0 + OFF_MB;

    const int tid = threadIdx.x;
    const int wid = tid >> 5;
    const int lane = tid & 31;
    const int warp_m = wid >> 2;     // 0..1  -> 64 rows
    const int warp_n = wid & 3;      // 0..3  -> 64 cols

    int* rows = (int*)(smraw + ((A0 + OFF_ROWS) - smem_u32(smraw)));
    if (tid < BM) rows[tid] = d_perm[m0p + tid];
    if (tid == 0) {
#pragma unroll
        for (int s = 0; s < STAGES; s++) MBARRIER_INIT(mb + s * 8, 1);
    }
    __syncthreads();

    if (tid == 0) {
#pragma unroll
        for (int s = 0; s < STAGES - 1; s++) issue_stage(A0, mb, s, s, mt, e, nt);
    }

    float acc[4][8][4];
#pragma unroll
    for (int i = 0; i < 4; i++)
#pragma unroll
        for (int j = 0; j < 8; j++)
#pragma unroll
            for (int q = 0; q < 4; q++) acc[i][j][q] = 0.0f;

    const int lrow = lane & 15;
    const int lc16 = (lane >> 4) << 4;

    for (int c = 0; c < NKC; c++) {
        const int s = c & (STAGES - 1);
        if (tid == 0 && c + STAGES - 1 < NKC)
            issue_stage(A0, mb, c + STAGES - 1, (c + STAGES - 1) & (STAGES - 1), mt, e, nt);

        MBARRIER_WAIT_PARITY(mb + s * 8, (c >> 2) & 1);

        const uint32_t aA = A0 + s * STAGE_SZ;
        const uint32_t aB = aA + OFF_B;
#pragma unroll
        for (int ks = 0; ks < 4; ks++) {
            uint32_t af[4][4];
#pragma unroll
            for (int i = 0; i < 4; i++)
                ldsm_x4(af[i], aA + sw128((uint32_t)((warp_m * 64 + i * 16 + lrow) * 128 + ks * 32 + lc16)));
            uint32_t bf[4][4];
#pragma unroll
            for (int g = 0; g < 4; g++)
                ldsm_x4(bf[g], aB + sw128((uint32_t)((warp_n * 64 + g * 16 + lrow) * 128 + ks * 32 + lc16)));
#pragma unroll
            for (int i = 0; i < 4; i++)
#pragma unroll
                for (int j = 0; j < 8; j++)
                    mma16816(acc[i][j], af[i], bf[j >> 1][j & 1], bf[j >> 1][(j & 1) + 2]);
        }
        __syncthreads();
    }

    // epilogue: add bias, scatter rows
    const float* be = bias + (size_t)e * DIM;
#pragma unroll
    for (int i = 0; i < 4; i++) {
#pragma unroll
        for (int half = 0; half < 2; half++) {
            int mloc = warp_m * 64 + i * 16 + (lane >> 2) + half * 8;
            int grow = rows[mloc];
            if (grow < 0) continue;
            float* orow = out + (size_t)grow * DIM;
#pragma unroll
            for (int j = 0; j < 8; j++) {
                int col = n0 + warp_n * 64 + j * 8 + (lane & 3) * 2;
                float2 bb = *(const float2*)(be + col);
                float2 o;
                o.x = acc[i][j][half * 2 + 0] + bb.x;
                o.y = acc[i][j][half * 2 + 1] + bb.y;
                *(float2*)(orow + col) = o;
            }
        }
    }
}

// ======================= host =======================
extern "C" void kernel_launch(void* const* d_in, const int* in_sizes, int n_in,
                              void* d_out, int out_size)
{
    const float* x = nullptr;
    const float* W = nullptr;
    const float* b = nullptr;
    const void* idx = nullptr;
    for (int i = 0; i < n_in; i++) {
        long long sz = in_sizes[i];
        if      (sz == (long long)B_TOK * DIM)      x = (const float*)d_in[i];
        else if (sz == (long long)NEXP * DIM * DIM) W = (const float*)d_in[i];
        else if (sz == (long long)NEXP * DIM)       b = (const float*)d_in[i];
        else if (sz == (long long)B_TOK)            idx = d_in[i];
    }
    float* out = (float*)d_out;
    const int* v32 = (const int*)idx;

    cudaFuncSetAttribute(k_gemm, cudaFuncAttributeMaxDynamicSharedMemorySize, SMEM_REQ);

    k_zero<<<MAXTILES * 128 / 256, 256>>>();
    k_detect<<<B_TOK / 256, 256>>>(v32);
    k_hist<<<B_TOK / 256, 256>>>(v32);
    k_scan<<<1, 1>>>();
    k_scatter<<<B_TOK / 256, 256>>>(v32);

    dim3 xgrid(MAXTILES, NKC);
    k_convx<<<xgrid, 256>>>(x);
    dim3 wgrid(NNT, NKC, NEXP);
    k_convw<<<wgrid, 256>>>(W);

    dim3 ggrid(NNT, MAXTILES);      // (8, 72); tiles beyond padded total exit
    k_gemm<<<ggrid, GTHREADS, SMEM_REQ>>>(b, out);
}